// round 16
// baseline (speedup 1.0000x reference)
#include <cuda_runtime.h>
#include <math.h>

constexpr int cB = 64, cT = 256, cE = 128, cDEG = 8, cHID = 100;
constexpr int cTM1 = 255, cNBUCKET = 288;
constexpr int cCH = 16;                // 16-t chunks per batch

// ---------------- device scratch ----------------
__device__ float g_Q [cB*cT*cE];
__device__ float g_K [cB*cT*cE];
__device__ float g_V [cB*cT*cE];
__device__ float g_Hc[cB*cT*cHID];
__device__ float g_WoW1[cE*cHID];
__device__ float g_Db[cB*cHID];
__device__ float g_Ad[cHID], g_Ax[cHID], g_Ay[cHID], g_Cv[cHID];
__device__ float g_u1[25], g_w1b[25];
__device__ float g_sparts[cB*3];
__device__ float g_pparts[cCH*cB];
__device__ int   g_done;

// ================= QKV GEMM (+gather) fused with setup blocks =================
__global__ __launch_bounds__(512)
void qkv_setup_kernel(const int* __restrict__ xsg, const float* __restrict__ emb,
                      const float* __restrict__ Wq, const float* __restrict__ Wk,
                      const float* __restrict__ Wv,
                      const int* __restrict__ lengths,
                      const float* __restrict__ Wo, const float* __restrict__ W1,
                      const int* __restrict__ dest,
                      const float* __restrict__ distW, const float* __restrict__ distb,
                      const float* __restrict__ dirW,  const float* __restrict__ dirb,
                      const float* __restrict__ ttW,   const float* __restrict__ ttb,
                      const float* __restrict__ obW1,  const float* __restrict__ omb1,
                      const int* __restrict__ adj, const int* __restrict__ seg,
                      const float* __restrict__ TD, const int* __restrict__ stp) {
    int tid = threadIdx.x;
    int by = blockIdx.y, bx = blockIdx.x;

    if (by >= 128) {
        if (bx != 0) return;
        int sg = by - 128;
        if (sg < 32) {                        // WoW1: 4 rows per block
            int row = sg*4 + (tid >> 7);
            int j = tid & 127;
            if (j < cHID) {
                float s = 0.f;
                for (int e = 0; e < cE; e++) s += Wo[row*cE + e] * W1[e*cHID + j];
                g_WoW1[row*cHID + j] = s;
            }
        } else if (sg < 48) {                 // Db: 4 batches per block
            int b = (sg - 32)*4 + (tid >> 7);
            int j = tid & 127;
            if (j < cHID) {
                int d = dest[b];
                float s = 0.f;
                for (int e = 0; e < cE; e++) s += emb[(long)d*cE + e] * W1[(228+e)*cHID + j];
                g_Db[b*cHID + j] = s;
            }
        } else if (sg == 48) {                // consts
            int j = tid;
            if (j == 0) g_done = 0;
            if (j < cHID) {
                float ad = 0, ax = 0, ay = 0, cv = omb1[j];
                for (int f = 0; f < 50; f++) {
                    float wd = W1[(128+f)*cHID + j];
                    float wr = W1[(178+f)*cHID + j];
                    ad += distW[f]*wd;  cv += distb[f]*wd;
                    ax += dirW[f]*wr;   ay += dirW[50+f]*wr;  cv += dirb[f]*wr;
                }
                g_Ad[j] = ad; g_Ax[j] = ax; g_Ay[j] = ay; g_Cv[j] = cv;
            }
            if (j >= 128 && j < 153) {
                int i = j - 128;
                float u = 0, w = 0;
                for (int f = 0; f < 50; f++) {
                    u += ttW[f]*obW1[f*25 + i];
                    w += ttb[f]*obW1[f*25 + i];
                }
                g_u1[i] = u; g_w1b[i] = w;
            }
        } else {                              // stats: 4 batches per block
            __shared__ float r0[512], r1[512], r2[512];
            int grp = tid >> 7, l = tid & 127;
            int b = (sg - 49)*4 + grp;
            int len = lengths[b], st = stp[0];
            float s = 0.f, ss = 0.f, c = 0.f;
            for (int i = l; i < cTM1*cDEG; i += 128) {
                int t = i >> 3;
                if (t >= len - 1) continue;
                int d = i & 7;
                int x = xsg[b*cT + t];
                int a = adj[x*cDEG + d];
                if (a != 0) {
                    float tt = TD[(long)seg[x*cDEG + d]*cNBUCKET + st];
                    s += tt; ss += tt*tt; c += 1.f;
                }
            }
            int base = grp*128;
            r0[base+l] = s; r1[base+l] = ss; r2[base+l] = c;
            __syncthreads();
            for (int o = 64; o > 0; o >>= 1) {
                if (l < o) {
                    r0[base+l] += r0[base+l+o];
                    r1[base+l] += r1[base+l+o];
                    r2[base+l] += r2[base+l+o];
                }
                __syncthreads();
            }
            if (l == 0) {
                g_sparts[b*3]   = r0[base];
                g_sparts[b*3+1] = r1[base];
                g_sparts[b*3+2] = r2[base];
            }
        }
        return;
    }

    // ---------------- QKV GEMM path ----------------
    int m0 = by * 128;
    int b  = m0 >> 8, t0 = m0 & 255;
    int len = lengths[b];
    if (t0 >= ((len + 63) & ~63)) return;
    const float* Bm = (bx == 0) ? Wq : (bx == 1 ? Wk : Wv);
    float*       C  = (bx == 0) ? g_Q : (bx == 1 ? g_K : g_V);

    __shared__ float As[128*17];
    __shared__ float Bs[17*128];
    __shared__ int   sXs[128];
    int tx = tid & 15, ty = tid >> 4;

    if (tid < 128) sXs[tid] = xsg[m0 + tid];
    __syncthreads();

    int rA = tid >> 2, cA = (tid & 3) * 4;
    const float* arow = emb + (long)sXs[rA]*cE;
    int rB = tid >> 5, cB2 = (tid & 31) * 4;

    float acc[4][8] = {};
    for (int k0 = 0; k0 < 128; k0 += 16) {
        {
            float4 v = *(const float4*)(arow + k0 + cA);
            float* as = As + rA*17 + cA;
            as[0]=v.x; as[1]=v.y; as[2]=v.z; as[3]=v.w;
        }
        {
            float4 v = *(const float4*)(Bm + (long)(k0 + rB)*cE + cB2);
            *(float4*)(Bs + rB*128 + cB2) = v;
        }
        __syncthreads();
        float ac[4], bc[8];
        #pragma unroll
        for (int i = 0; i < 4; i++) ac[i] = As[(ty*4 + i)*17];
        {
            float4 u0 = *(float4*)(Bs + tx*4), u1 = *(float4*)(Bs + 64 + tx*4);
            bc[0]=u0.x; bc[1]=u0.y; bc[2]=u0.z; bc[3]=u0.w;
            bc[4]=u1.x; bc[5]=u1.y; bc[6]=u1.z; bc[7]=u1.w;
        }
        #pragma unroll
        for (int kk = 0; kk < 16; kk += 2) {
            float an[4], bn[8];
            #pragma unroll
            for (int i = 0; i < 4; i++) an[i] = As[(ty*4 + i)*17 + kk + 1];
            {
                float4 u0 = *(float4*)(Bs + (kk+1)*128 + tx*4);
                float4 u1 = *(float4*)(Bs + (kk+1)*128 + 64 + tx*4);
                bn[0]=u0.x; bn[1]=u0.y; bn[2]=u0.z; bn[3]=u0.w;
                bn[4]=u1.x; bn[5]=u1.y; bn[6]=u1.z; bn[7]=u1.w;
            }
            #pragma unroll
            for (int i = 0; i < 4; i++)
                #pragma unroll
                for (int j = 0; j < 8; j++)
                    acc[i][j] += ac[i]*bc[j];
            #pragma unroll
            for (int i = 0; i < 4; i++) ac[i] = As[(ty*4 + i)*17 + kk + 2];
            {
                float4 u0 = *(float4*)(Bs + (kk+2)*128 + tx*4);
                float4 u1 = *(float4*)(Bs + (kk+2)*128 + 64 + tx*4);
                bc[0]=u0.x; bc[1]=u0.y; bc[2]=u0.z; bc[3]=u0.w;
                bc[4]=u1.x; bc[5]=u1.y; bc[6]=u1.z; bc[7]=u1.w;
            }
            #pragma unroll
            for (int i = 0; i < 4; i++)
                #pragma unroll
                for (int j = 0; j < 8; j++)
                    acc[i][j] += an[i]*bn[j];
        }
        __syncthreads();
    }
    if (bx == 0) {
        const float scale = 0.08838834764831845f;
        #pragma unroll
        for (int i = 0; i < 4; i++)
            #pragma unroll
            for (int j = 0; j < 8; j++)
                acc[i][j] *= scale;
    }
    #pragma unroll
    for (int i = 0; i < 4; i++) {
        int row = m0 + ty*4 + i;
        float* cp = C + (long)row*cE;
        *(float4*)(cp + tx*4)      = make_float4(acc[i][0],acc[i][1],acc[i][2],acc[i][3]);
        *(float4*)(cp + 64 + tx*4) = make_float4(acc[i][4],acc[i][5],acc[i][6],acc[i][7]);
    }
}

// ================= flash attention, 32-row q-tiles + fused Hc epilogue =================
__global__ __launch_bounds__(256)
void attn_kernel(const int* __restrict__ lengths) {
    extern __shared__ float sm[];
    float* Qs  = sm;                       // 32x32 float4, swizzled
    float* KVs = sm + 32*128;              // K/V tiles; later Os[32][132]
    float* Ps  = sm + 32*128 + 64*128;     // [32][68]; later Bs[16][64]

    int b  = blockIdx.y;
    int qt = 7 - blockIdx.x;
    int q0 = qt * 32;
    int len = lengths[b];
    if (q0 >= len) return;

    int tid = threadIdx.x;
    int tx = tid & 15, ty = tid >> 4;
    float4* Q4  = (float4*)Qs;
    float4* KV4 = (float4*)KVs;
    float4* P4  = (float4*)Ps;
    int swa = (ty >> 1) & 7;
    int swb = tx & 7;

    const float4* Qg = (const float4*)(g_Q + (long)(b*cT + q0)*cE);
    #pragma unroll
    for (int i = 0; i < 4; i++) {
        int idx = tid + i*256;
        int r = idx >> 5, c = idx & 31;
        Q4[r*32 + (c ^ ((r>>2)&7))] = Qg[r*32 + c];
    }
    float O[2][8] = {};
    float mr[2], lr[2];
    #pragma unroll
    for (int i = 0; i < 2; i++) { mr[i] = -1e30f; lr[i] = 0.f; }
    __syncthreads();

    int ktmax = min(q0 >> 6, ((len + 63) >> 6) - 1);
    for (int kt = 0; kt <= ktmax; kt++) {
        const float4* Kg = (const float4*)(g_K + (long)(b*cT + kt*64)*cE);
        #pragma unroll
        for (int i = 0; i < 8; i++) {
            int idx = tid + i*256;
            int r = idx >> 5, c = idx & 31;
            KV4[r*32 + (c ^ ((r>>2)&7))] = Kg[r*32 + c];
        }
        __syncthreads();
        float s[2][4] = {};
        #pragma unroll 4
        for (int c = 0; c < 32; c++) {
            float4 a4[2], b4[4];
            #pragma unroll
            for (int i = 0; i < 2; i++) a4[i] = Q4[(ty*2 + i)*32 + (c ^ swa)];
            #pragma unroll
            for (int j = 0; j < 4; j++) b4[j] = KV4[(tx*4 + j)*32 + (c ^ swb)];
            #pragma unroll
            for (int i = 0; i < 2; i++)
                #pragma unroll
                for (int j = 0; j < 4; j++) {
                    s[i][j] += a4[i].x*b4[j].x;
                    s[i][j] += a4[i].y*b4[j].y;
                    s[i][j] += a4[i].z*b4[j].z;
                    s[i][j] += a4[i].w*b4[j].w;
                }
        }
        int kbase = kt*64;
        #pragma unroll
        for (int i = 0; i < 2; i++) {
            int q = q0 + ty*2 + i;
            #pragma unroll
            for (int j = 0; j < 4; j++) {
                int k = kbase + tx*4 + j;
                if (k > q || k >= len) s[i][j] = -1e30f;
            }
        }
        #pragma unroll
        for (int i = 0; i < 2; i++) {
            float m2 = fmaxf(fmaxf(s[i][0], s[i][1]), fmaxf(s[i][2], s[i][3]));
            #pragma unroll
            for (int o = 1; o < 16; o <<= 1)
                m2 = fmaxf(m2, __shfl_xor_sync(0xffffffffu, m2, o));
            float mn = fmaxf(mr[i], m2);
            float al = __expf(mr[i] - mn);
            mr[i] = mn;
            float r = 0.f;
            #pragma unroll
            for (int j = 0; j < 4; j++) {
                float p = __expf(s[i][j] - mn);
                s[i][j] = p; r += p;
            }
            #pragma unroll
            for (int o = 1; o < 16; o <<= 1)
                r += __shfl_xor_sync(0xffffffffu, r, o);
            lr[i] = lr[i]*al + r;
            #pragma unroll
            for (int j = 0; j < 8; j++) O[i][j] *= al;
        }
        #pragma unroll
        for (int i = 0; i < 2; i++)
            #pragma unroll
            for (int j = 0; j < 4; j++)
                Ps[(ty*2 + i)*68 + tx*4 + j] = s[i][j];
        __syncthreads();
        const float4* Vg = (const float4*)(g_V + (long)(b*cT + kt*64)*cE);
        #pragma unroll
        for (int i = 0; i < 8; i++) {
            int idx = tid + i*256;
            int r = idx >> 5, c = idx & 31;
            KV4[r*32 + (c ^ ((r>>2)&7))] = Vg[r*32 + c];
        }
        __syncthreads();
        #pragma unroll 2
        for (int c4 = 0; c4 < 16; c4++) {
            float4 p4[2];
            #pragma unroll
            for (int i = 0; i < 2; i++) p4[i] = P4[(ty*2 + i)*17 + c4];
            int X = c4 & 7;
            #pragma unroll
            for (int m = 0; m < 4; m++) {
                int kk = c4*4 + m;
                float4 v0 = KV4[kk*32 + (tx ^ X)];
                float4 v1 = KV4[kk*32 + ((tx + 16) ^ X)];
                #pragma unroll
                for (int i = 0; i < 2; i++) {
                    float p = (m == 0) ? p4[i].x : (m == 1) ? p4[i].y
                            : (m == 2) ? p4[i].z : p4[i].w;
                    O[i][0] += p*v0.x; O[i][1] += p*v0.y;
                    O[i][2] += p*v0.z; O[i][3] += p*v0.w;
                    O[i][4] += p*v1.x; O[i][5] += p*v1.y;
                    O[i][6] += p*v1.z; O[i][7] += p*v1.w;
                }
            }
        }
        __syncthreads();
    }

    // ---- normalized O into Os (KVs reuse, stride 132) ----
    #pragma unroll
    for (int i = 0; i < 2; i++) {
        float inv = 1.f / lr[i];
        float* orow = KVs + (ty*2 + i)*132;
        *(float4*)(orow + tx*4)      = make_float4(O[i][0]*inv, O[i][1]*inv, O[i][2]*inv, O[i][3]*inv);
        *(float4*)(orow + 64 + tx*4) = make_float4(O[i][4]*inv, O[i][5]*inv, O[i][6]*inv, O[i][7]*inv);
    }
    __syncthreads();

    // ---- Hc[q0..q0+31][0..99] = Os @ WoW1, two 64-col passes ----
    float* Bse = Ps;                      // [16][64]
    int rB = tid >> 4, cB4 = (tid & 15)*4;
    #pragma unroll
    for (int cpass = 0; cpass < 2; cpass++) {
        int colbase = cpass*64;
        float acc2[2][4] = {};
        for (int k0 = 0; k0 < 128; k0 += 16) {
            #pragma unroll
            for (int u = 0; u < 4; u++) {
                int col = colbase + cB4 + u;
                Bse[rB*64 + cB4 + u] = (col < cHID) ? g_WoW1[(k0 + rB)*cHID + col] : 0.f;
            }
            __syncthreads();
            #pragma unroll
            for (int kk = 0; kk < 16; kk++) {
                float a0 = KVs[(ty*2)*132 + k0 + kk];
                float a1 = KVs[(ty*2 + 1)*132 + k0 + kk];
                float4 bb = *(float4*)(Bse + kk*64 + tx*4);
                acc2[0][0] += a0*bb.x; acc2[0][1] += a0*bb.y;
                acc2[0][2] += a0*bb.z; acc2[0][3] += a0*bb.w;
                acc2[1][0] += a1*bb.x; acc2[1][1] += a1*bb.y;
                acc2[1][2] += a1*bb.z; acc2[1][3] += a1*bb.w;
            }
            __syncthreads();
        }
        int col = colbase + tx*4;
        if (col < cHID) {
            #pragma unroll
            for (int i = 0; i < 2; i++) {
                float* hp = g_Hc + (long)(b*cT + q0 + ty*2 + i)*cHID + col;
                *(float4*)hp = make_float4(acc2[i][0], acc2[i][1], acc2[i][2], acc2[i][3]);
            }
        }
    }
}

// ================= MLP: k-major As, 4 blocks/SM, two 64-row passes =================
__global__ __launch_bounds__(256, 4)
void mlp_kernel(const int* __restrict__ xs, const int* __restrict__ lengths,
                const int* __restrict__ acts, const int* __restrict__ dest,
                const int* __restrict__ adj, const int* __restrict__ seg,
                const int* __restrict__ stp, const float* __restrict__ loc,
                const float* __restrict__ TD,
                const float* __restrict__ W2, const float* __restrict__ b2,
                const float* __restrict__ W3, const float* __restrict__ b3,
                const float* __restrict__ obb1, const float* __restrict__ obW2,
                const float* __restrict__ obb2, float* __restrict__ out) {
    extern __shared__ float sh[];
    float* Bs    = sh;                 // [100][64]   k-major
    float* As    = sh + 100*64;        // [100][64]   k-major h1
    float* sFeat = As + 100*64;        // [128] float4
    float* sP4   = sFeat + 128*4;      // [100] float4
    float* sW3   = sP4 + 400;          // [64]
    float* sB2   = sW3 + 64;           // [64]
    float* sLog  = sB2 + 64;           // [64]
    float* sMisc = sLog + 64;          // [4]
    // aliases into As (dead before first h1 fill):
    float* sSt = As;                   // [192]
    float* sSm = As + 192;             // [100]
    __shared__ int sLast;
    __shared__ float rr[64];

    int b = blockIdx.y;
    int len = lengths[b];
    int t0 = blockIdx.x * 16;
    int tid = threadIdx.x;
    bool active = (t0 < len - 1);
    float bsum = 0.f;

    if (active) {
        int tmax = min(t0 + 16, len - 1);
        // ---- phase A: loads ----
        for (int i = tid; i < 100*64; i += 256) {
            int k = i >> 6, n = i & 63;
            Bs[i] = (n < 50) ? W2[k*50 + n] : 0.f;
        }
        if (tid < cHID) {
            sP4[tid*4 + 0] = g_Db[b*cHID + tid] + g_Cv[tid];
            sP4[tid*4 + 1] = g_Ad[tid];
            sP4[tid*4 + 2] = g_Ax[tid];
            sP4[tid*4 + 3] = g_Ay[tid];
        }
        if (tid >= 128 && tid < 192) {
            int j = tid - 128;
            sW3[j] = (j < 50) ? W3[j] : 0.f;
            sB2[j] = (j < 50) ? b2[j] : 0.f;
        }
        if (tid >= 192) {
            int j = tid - 192;
            sSt[j]      = g_sparts[j*3];
            sSt[64+j]   = g_sparts[j*3+1];
            sSt[128+j]  = g_sparts[j*3+2];
        }
        if (tid >= 100 && tid < 125) {
            int i = tid - 100;
            sSm[i]    = g_u1[i];  sSm[25+i] = g_w1b[i];
            sSm[50+i] = obW2[i];  sSm[75+i] = obb1[i];
        }
        if (tid == 125) sMisc[2] = b3[0] + obb2[0];
        __syncthreads();
        if (tid == 0) {
            float s = 0.f, ss = 0.f, c = 0.f;
            for (int i = 0; i < 64; i++) { s += sSt[i]; ss += sSt[64+i]; c += sSt[128+i]; }
            float mean = s / c;
            float var = (ss - c*mean*mean) / (c - 1.f);
            sMisc[0] = mean;
            sMisc[1] = 1.f / (sqrtf(var) + 1e-6f);
        }
        __syncthreads();

        // ---- phase B: per-row features + ob ----
        if (tid < 128) {
            int tl = tid >> 3, d = tid & 7;
            int t = t0 + tl;
            int x = xs[b*cT + t];
            int nb = adj[x*cDEG + d];
            int db_ = dest[b];
            float nx = loc[nb*2], ny = loc[nb*2 + 1];
            float dx = loc[db_*2], dy = loc[db_*2 + 1];
            float cx = loc[x*2],  cy = loc[x*2 + 1];
            float dist = (fabsf(nx - dx) + fabsf(ny - dy)) * 100.f;
            float vx = nx - cx, vy = ny - cy;
            float inv = 1.f / (sqrtf(vx*vx + vy*vy) + 1e-8f);
            float mf = (nb != 0) ? 1.f : 0.f;
            float tt = TD[(long)seg[x*cDEG + d]*cNBUCKET + stp[0]];
            float ttw = (tt - sMisc[0]) * sMisc[1];
            float ob = 0.f;
            #pragma unroll
            for (int i = 0; i < 25; i++) {
                float z = mf*(ttw*sSm[i] + sSm[25+i]) + sSm[75+i];
                ob += fmaxf(z, 0.f) * sSm[50+i];
            }
            ((float4*)sFeat)[tid] = make_float4(dist, vx*inv, vy*inv, ob);
        }
        __syncthreads();

        int tx = tid & 15, ty = tid >> 4;
        float w3v[4], b2v[4];
        #pragma unroll
        for (int j = 0; j < 4; j++) { w3v[j] = sW3[tx*4 + j]; b2v[j] = sB2[tx*4 + j]; }
        float lb = sMisc[2];
        int frow = tid & 63;           // h1-fill row
        int k0f  = tid >> 6;           // h1-fill k phase (0..3)

        #pragma unroll
        for (int pass = 0; pass < 2; pass++) {
            int rbase = pass*64;
            // ---- h1 fill (k-major): As[k][frow] ----
            {
                float4 f = ((float4*)sFeat)[rbase + frow];
                const float* HcRow = g_Hc +
                    ((long)(b*cT + t0) + ((rbase + frow) >> 3))*cHID;
                #pragma unroll
                for (int i = 0; i < 25; i++) {
                    int k = k0f + 4*i;
                    float4 p = ((float4*)sP4)[k];
                    float h = HcRow[k] + p.x + f.x*p.y + f.y*p.z + f.z*p.w;
                    As[k*64 + frow] = fmaxf(h, 0.f);
                }
            }
            __syncthreads();
            // ---- GEMM 64x64x100: 4 LDS.128 per 32 FMA ----
            const float4* A4 = (const float4*)As;
            const float4* B4 = (const float4*)Bs;
            float acc[4][4] = {};
            #pragma unroll 5
            for (int c2 = 0; c2 < 50; c2++) {
                float4 a0 = A4[(2*c2)*16 + ty];
                float4 a1 = A4[(2*c2 + 1)*16 + ty];
                float4 b0 = B4[(2*c2)*16 + tx];
                float4 b1 = B4[(2*c2 + 1)*16 + tx];
                acc[0][0] += a0.x*b0.x; acc[0][1] += a0.x*b0.y;
                acc[0][2] += a0.x*b0.z; acc[0][3] += a0.x*b0.w;
                acc[1][0] += a0.y*b0.x; acc[1][1] += a0.y*b0.y;
                acc[1][2] += a0.y*b0.z; acc[1][3] += a0.y*b0.w;
                acc[2][0] += a0.z*b0.x; acc[2][1] += a0.z*b0.y;
                acc[2][2] += a0.z*b0.z; acc[2][3] += a0.z*b0.w;
                acc[3][0] += a0.w*b0.x; acc[3][1] += a0.w*b0.y;
                acc[3][2] += a0.w*b0.z; acc[3][3] += a0.w*b0.w;
                acc[0][0] += a1.x*b1.x; acc[0][1] += a1.x*b1.y;
                acc[0][2] += a1.x*b1.z; acc[0][3] += a1.x*b1.w;
                acc[1][0] += a1.y*b1.x; acc[1][1] += a1.y*b1.y;
                acc[1][2] += a1.y*b1.z; acc[1][3] += a1.y*b1.w;
                acc[2][0] += a1.z*b1.x; acc[2][1] += a1.z*b1.y;
                acc[2][2] += a1.z*b1.z; acc[2][3] += a1.z*b1.w;
                acc[3][0] += a1.w*b1.x; acc[3][1] += a1.w*b1.y;
                acc[3][2] += a1.w*b1.z; acc[3][3] += a1.w*b1.w;
            }
            // ---- epilogue: relu + W3 dot, 16-lane reduce ----
            #pragma unroll
            for (int i = 0; i < 4; i++) {
                float part = 0.f;
                #pragma unroll
                for (int j = 0; j < 4; j++)
                    part += fmaxf(acc[i][j] + b2v[j], 0.f) * w3v[j];
                #pragma unroll
                for (int o = 8; o > 0; o >>= 1)
                    part += __shfl_xor_sync(0xffffffffu, part, o);
                if (tx == 0) {
                    int row = ty*4 + i;
                    sLog[row] = part + ((float4*)sFeat)[rbase + row].w + lb;
                }
            }
            __syncthreads();
            // ---- NLL for this pass's 8 t ----
            if (tid < 32) {
                float nll = 0.f;
                if (tid < 8) {
                    int t = t0 + pass*8 + tid;
                    if (t < tmax) {
                        float l0[8];
                        #pragma unroll
                        for (int i = 0; i < 8; i++) l0[i] = sLog[tid*8 + i];
                        float m = l0[0];
                        #pragma unroll
                        for (int i = 1; i < 8; i++) m = fmaxf(m, l0[i]);
                        float s = 0.f;
                        #pragma unroll
                        for (int i = 0; i < 8; i++) s += __expf(l0[i] - m);
                        int a = acts[b*cTM1 + t];
                        nll = (m + __logf(s)) - l0[a];
                    }
                }
                bsum += nll;
            }
        }
        if (tid < 32) {
            #pragma unroll
            for (int o = 16; o > 0; o >>= 1)
                bsum += __shfl_xor_sync(0xffffffffu, bsum, o);
            if (tid == 0) g_pparts[blockIdx.x*cB + b] = bsum;
        }
    } else {
        if (tid == 0) g_pparts[blockIdx.x*cB + b] = 0.f;
    }

    // ---- completion counter + fused final reduce ----
    __syncthreads();
    __threadfence();
    if (tid == 0) {
        int n = atomicAdd(&g_done, 1);
        sLast = (n == cCH*cB - 1) ? 1 : 0;
    }
    __syncthreads();
    if (sLast) {
        __threadfence();
        if (tid < 64) {
            float s = 0.f;
            #pragma unroll
            for (int c = 0; c < cCH; c++) s += g_pparts[c*cB + tid];
            rr[tid] = s / (float)(lengths[tid] - 1);
        }
        __syncthreads();
        for (int o = 32; o > 0; o >>= 1) {
            if (tid < o && tid + o < 64) rr[tid] += rr[tid + o];
            __syncthreads();
        }
        if (tid == 0) out[0] = rr[0];
    }
}

// ---------------- launch ----------------
extern "C" void kernel_launch(void* const* d_in, const int* in_sizes, int n_in,
                              void* d_out, int out_size) {
    const int*   xs      = (const int*)  d_in[0];
    const int*   lengths = (const int*)  d_in[1];
    const int*   acts    = (const int*)  d_in[2];
    const int*   dest    = (const int*)  d_in[3];
    const int*   adj     = (const int*)  d_in[4];
    const int*   seg     = (const int*)  d_in[5];
    const int*   stp     = (const int*)  d_in[6];
    const float* loc     = (const float*)d_in[7];
    const float* TD      = (const float*)d_in[8];
    const float* emb     = (const float*)d_in[9];
    const float* Wq      = (const float*)d_in[10];
    const float* Wk      = (const float*)d_in[11];
    const float* Wv      = (const float*)d_in[12];
    const float* Wo      = (const float*)d_in[13];
    const float* distW   = (const float*)d_in[14];
    const float* distb   = (const float*)d_in[15];
    const float* dirW    = (const float*)d_in[16];
    const float* dirb    = (const float*)d_in[17];
    const float* ttW     = (const float*)d_in[18];
    const float* ttb     = (const float*)d_in[19];
    const float* obW1    = (const float*)d_in[20];
    const float* obb1    = (const float*)d_in[21];
    const float* obW2    = (const float*)d_in[22];
    const float* obb2    = (const float*)d_in[23];
    const float* W1      = (const float*)d_in[24];
    const float* omb1    = (const float*)d_in[25];
    const float* W2      = (const float*)d_in[26];
    const float* b2      = (const float*)d_in[27];
    const float* W3      = (const float*)d_in[28];
    const float* b3      = (const float*)d_in[29];

    const int ASMEM = (32*128 + 64*128 + 32*68) * 4;   // 57856 B
    cudaFuncSetAttribute(attn_kernel, cudaFuncAttributeMaxDynamicSharedMemorySize, ASMEM);
    const int MSMEM = (100*64 + 100*64 + 128*4 + 100*4 + 64 + 64 + 64 + 4) * 4; // 55536 B
    cudaFuncSetAttribute(mlp_kernel, cudaFuncAttributeMaxDynamicSharedMemorySize, MSMEM);

    // 1) fused gather+QKV GEMM with setup riding along
    qkv_setup_kernel<<<dim3(3, 128 + 65), 512>>>(
        xs, emb, Wq, Wk, Wv, lengths,
        Wo, W1, dest, distW, distb, dirW, dirb, ttW, ttb, obW1, omb1,
        adj, seg, TD, stp);

    // 2) flash attention + fused Hc epilogue
    attn_kernel<<<dim3(8, cB), 256, ASMEM>>>(lengths);

    // 3) MLP + NLL + fused final reduction
    mlp_kernel<<<dim3(cCH, cB), 256, MSMEM>>>(xs, lengths, acts, dest, adj, seg, stp,
                                              loc, TD, W2, b2, W3, b3,
                                              obb1, obW2, obb2, (float*)d_out);
}

// round 17
// speedup vs baseline: 1.1967x; 1.1967x over previous
#include <cuda_runtime.h>
#include <math.h>

constexpr int cB = 64, cT = 256, cE = 128, cDEG = 8, cHID = 100;
constexpr int cTM1 = 255, cNBUCKET = 288;
constexpr int cCH = 16;                // 16-t chunks per batch

// ---------------- device scratch ----------------
__device__ float g_Q [cB*cT*cE];
__device__ float g_K [cB*cT*cE];
__device__ float g_V [cB*cT*cE];
__device__ float g_AH[cB*cT*cE];
__device__ float g_Hc[cB*cT*cHID];
__device__ float g_WoW1[cE*cHID];
__device__ float g_Db[cB*cHID];
__device__ float g_Ad[cHID], g_Ax[cHID], g_Ay[cHID], g_Cv[cHID];
__device__ float g_u1[25], g_w1b[25];
__device__ float g_sparts[cB*3];
__device__ float g_pparts[cCH*cB];
__device__ int   g_done;

// ================= QKV GEMM (64-row tiles) + setup tail =================
// grid (3, 256+161), 256 threads.
// by<256: QKV 64-row tile. by>=256 (bx==0 only): setup work.
__global__ __launch_bounds__(256)
void qkv_setup_kernel(const int* __restrict__ xsg, const float* __restrict__ emb,
                      const float* __restrict__ Wq, const float* __restrict__ Wk,
                      const float* __restrict__ Wv,
                      const int* __restrict__ lengths,
                      const float* __restrict__ Wo, const float* __restrict__ W1,
                      const int* __restrict__ dest,
                      const float* __restrict__ distW, const float* __restrict__ distb,
                      const float* __restrict__ dirW,  const float* __restrict__ dirb,
                      const float* __restrict__ ttW,   const float* __restrict__ ttb,
                      const float* __restrict__ obW1,  const float* __restrict__ omb1,
                      const int* __restrict__ adj, const int* __restrict__ seg,
                      const float* __restrict__ TD, const int* __restrict__ stp) {
    int tid = threadIdx.x;
    int by = blockIdx.y, bx = blockIdx.x;

    if (by >= 256) {
        if (bx != 0) return;
        int sg = by - 256;
        if (sg < 64) {                        // WoW1: 2 rows per block
            int row = sg*2 + (tid >> 7);
            int j = tid & 127;
            if (j < cHID) {
                float s = 0.f;
                for (int e = 0; e < cE; e++) s += Wo[row*cE + e] * W1[e*cHID + j];
                g_WoW1[row*cHID + j] = s;
            }
        } else if (sg < 96) {                 // Db: 2 batches per block
            int b = (sg - 64)*2 + (tid >> 7);
            int j = tid & 127;
            if (j < cHID) {
                int d = dest[b];
                float s = 0.f;
                for (int e = 0; e < cE; e++) s += emb[(long)d*cE + e] * W1[(228+e)*cHID + j];
                g_Db[b*cHID + j] = s;
            }
        } else if (sg == 96) {                // consts
            int j = tid;
            if (j == 0) g_done = 0;
            if (j < cHID) {
                float ad = 0, ax = 0, ay = 0, cv = omb1[j];
                for (int f = 0; f < 50; f++) {
                    float wd = W1[(128+f)*cHID + j];
                    float wr = W1[(178+f)*cHID + j];
                    ad += distW[f]*wd;  cv += distb[f]*wd;
                    ax += dirW[f]*wr;   ay += dirW[50+f]*wr;  cv += dirb[f]*wr;
                }
                g_Ad[j] = ad; g_Ax[j] = ax; g_Ay[j] = ay; g_Cv[j] = cv;
            }
            if (j >= 128 && j < 153) {
                int i = j - 128;
                float u = 0, w = 0;
                for (int f = 0; f < 50; f++) {
                    u += ttW[f]*obW1[f*25 + i];
                    w += ttb[f]*obW1[f*25 + i];
                }
                g_u1[i] = u; g_w1b[i] = w;
            }
        } else {                              // stats: 1 batch per block, 256 thr
            __shared__ float r0[256], r1[256], r2[256];
            int b = sg - 97;                  // sg 97..160
            int len = lengths[b], st = stp[0];
            float s = 0.f, ss = 0.f, c = 0.f;
            for (int i = tid; i < cTM1*cDEG; i += 256) {
                int t = i >> 3;
                if (t >= len - 1) continue;
                int d = i & 7;
                int x = xsg[b*cT + t];
                int a = adj[x*cDEG + d];
                if (a != 0) {
                    float tt = TD[(long)seg[x*cDEG + d]*cNBUCKET + st];
                    s += tt; ss += tt*tt; c += 1.f;
                }
            }
            r0[tid] = s; r1[tid] = ss; r2[tid] = c;
            __syncthreads();
            for (int o = 128; o > 0; o >>= 1) {
                if (tid < o) { r0[tid] += r0[tid+o]; r1[tid] += r1[tid+o]; r2[tid] += r2[tid+o]; }
                __syncthreads();
            }
            if (tid == 0) {
                g_sparts[b*3]   = r0[0];
                g_sparts[b*3+1] = r1[0];
                g_sparts[b*3+2] = r2[0];
            }
        }
        return;
    }

    // ---------------- QKV GEMM path: 64-row tile ----------------
    int m0 = by * 64;
    int b  = m0 >> 8, t0 = m0 & 255;
    int len = lengths[b];
    if (t0 >= ((len + 63) & ~63)) return;
    const float* Bm = (bx == 0) ? Wq : (bx == 1 ? Wk : Wv);
    float*       C  = (bx == 0) ? g_Q : (bx == 1 ? g_K : g_V);

    __shared__ float As[64*17];
    __shared__ float Bs[17*128];
    __shared__ int   sXs[64];
    int tx = tid & 15, ty = tid >> 4;     // ty 0..15 -> 4 rows each

    if (tid < 64) sXs[tid] = xsg[m0 + tid];
    __syncthreads();

    int rA = tid >> 2, cA = (tid & 3) * 4;       // 64 rows x 16 cols, 1 float4/thread
    const float* arow = emb + (long)sXs[rA]*cE;
    int rB = tid >> 4, cB2 = (tid & 15) * 8;     // 16 rows x 128 cols, 2 float4/thread

    float acc[4][8] = {};
    for (int k0 = 0; k0 < 128; k0 += 16) {
        {
            float4 v = *(const float4*)(arow + k0 + cA);
            float* as = As + rA*17 + cA;
            as[0]=v.x; as[1]=v.y; as[2]=v.z; as[3]=v.w;
        }
        {
            const float* bp = Bm + (long)(k0 + rB)*cE + cB2;
            *(float4*)(Bs + rB*128 + cB2)     = *(const float4*)bp;
            *(float4*)(Bs + rB*128 + cB2 + 4) = *(const float4*)(bp + 4);
        }
        __syncthreads();
        float ac[4], bc[8];
        #pragma unroll
        for (int i = 0; i < 4; i++) ac[i] = As[(ty*4 + i)*17];
        {
            float4 u0 = *(float4*)(Bs + tx*4), u1 = *(float4*)(Bs + 64 + tx*4);
            bc[0]=u0.x; bc[1]=u0.y; bc[2]=u0.z; bc[3]=u0.w;
            bc[4]=u1.x; bc[5]=u1.y; bc[6]=u1.z; bc[7]=u1.w;
        }
        #pragma unroll
        for (int kk = 0; kk < 16; kk += 2) {
            float an[4], bn[8];
            #pragma unroll
            for (int i = 0; i < 4; i++) an[i] = As[(ty*4 + i)*17 + kk + 1];
            {
                float4 u0 = *(float4*)(Bs + (kk+1)*128 + tx*4);
                float4 u1 = *(float4*)(Bs + (kk+1)*128 + 64 + tx*4);
                bn[0]=u0.x; bn[1]=u0.y; bn[2]=u0.z; bn[3]=u0.w;
                bn[4]=u1.x; bn[5]=u1.y; bn[6]=u1.z; bn[7]=u1.w;
            }
            #pragma unroll
            for (int i = 0; i < 4; i++)
                #pragma unroll
                for (int j = 0; j < 8; j++)
                    acc[i][j] += ac[i]*bc[j];
            #pragma unroll
            for (int i = 0; i < 4; i++) ac[i] = As[(ty*4 + i)*17 + kk + 2];  // pad col
            {
                float4 u0 = *(float4*)(Bs + (kk+2)*128 + tx*4);              // pad row
                float4 u1 = *(float4*)(Bs + (kk+2)*128 + 64 + tx*4);
                bc[0]=u0.x; bc[1]=u0.y; bc[2]=u0.z; bc[3]=u0.w;
                bc[4]=u1.x; bc[5]=u1.y; bc[6]=u1.z; bc[7]=u1.w;
            }
            #pragma unroll
            for (int i = 0; i < 4; i++)
                #pragma unroll
                for (int j = 0; j < 8; j++)
                    acc[i][j] += an[i]*bn[j];
        }
        __syncthreads();
    }
    if (bx == 0) {
        const float scale = 0.08838834764831845f;   // fold 1/sqrt(E) into Q
        #pragma unroll
        for (int i = 0; i < 4; i++)
            #pragma unroll
            for (int j = 0; j < 8; j++)
                acc[i][j] *= scale;
    }
    #pragma unroll
    for (int i = 0; i < 4; i++) {
        int row = m0 + ty*4 + i;
        float* cp = C + (long)row*cE;
        *(float4*)(cp + tx*4)      = make_float4(acc[i][0],acc[i][1],acc[i][2],acc[i][3]);
        *(float4*)(cp + 64 + tx*4) = make_float4(acc[i][4],acc[i][5],acc[i][6],acc[i][7]);
    }
}

// ================= Hc GEMM: AH @ WoW1 (N=100), 512 threads =================
__global__ __launch_bounds__(512)
void hc_gemm(const int* __restrict__ lengths) {
    int m0 = blockIdx.y * 128;
    int b  = m0 >> 8, t0 = m0 & 255;
    int len = lengths[b];
    if (t0 >= len - 1) return;
    const int N = cHID;

    __shared__ float As[128*17];
    __shared__ float Bs[17*128];
    int tid = threadIdx.x;
    int tx = tid & 15, ty = tid >> 4;

    int rA = tid >> 2, cA = (tid & 3) * 4;
    const float* arow = g_AH + (long)(m0 + rA)*cE;
    int rB = tid >> 5, cB2 = (tid & 31) * 4;

    float acc[4][8] = {};
    for (int k0 = 0; k0 < 128; k0 += 16) {
        {
            float4 v = *(const float4*)(arow + k0 + cA);
            float* as = As + rA*17 + cA;
            as[0]=v.x; as[1]=v.y; as[2]=v.z; as[3]=v.w;
        }
        {
            float4 z = make_float4(0.f,0.f,0.f,0.f);
            float4 v = (cB2 < N) ? *(const float4*)(g_WoW1 + (long)(k0 + rB)*N + cB2) : z;
            *(float4*)(Bs + rB*128 + cB2) = v;
        }
        __syncthreads();
        float ac[4], bc[8];
        #pragma unroll
        for (int i = 0; i < 4; i++) ac[i] = As[(ty*4 + i)*17];
        {
            float4 u0 = *(float4*)(Bs + tx*4), u1 = *(float4*)(Bs + 64 + tx*4);
            bc[0]=u0.x; bc[1]=u0.y; bc[2]=u0.z; bc[3]=u0.w;
            bc[4]=u1.x; bc[5]=u1.y; bc[6]=u1.z; bc[7]=u1.w;
        }
        #pragma unroll
        for (int kk = 0; kk < 16; kk += 2) {
            float an[4], bn[8];
            #pragma unroll
            for (int i = 0; i < 4; i++) an[i] = As[(ty*4 + i)*17 + kk + 1];
            {
                float4 u0 = *(float4*)(Bs + (kk+1)*128 + tx*4);
                float4 u1 = *(float4*)(Bs + (kk+1)*128 + 64 + tx*4);
                bn[0]=u0.x; bn[1]=u0.y; bn[2]=u0.z; bn[3]=u0.w;
                bn[4]=u1.x; bn[5]=u1.y; bn[6]=u1.z; bn[7]=u1.w;
            }
            #pragma unroll
            for (int i = 0; i < 4; i++)
                #pragma unroll
                for (int j = 0; j < 8; j++)
                    acc[i][j] += ac[i]*bc[j];
            #pragma unroll
            for (int i = 0; i < 4; i++) ac[i] = As[(ty*4 + i)*17 + kk + 2];
            {
                float4 u0 = *(float4*)(Bs + (kk+2)*128 + tx*4);
                float4 u1 = *(float4*)(Bs + (kk+2)*128 + 64 + tx*4);
                bc[0]=u0.x; bc[1]=u0.y; bc[2]=u0.z; bc[3]=u0.w;
                bc[4]=u1.x; bc[5]=u1.y; bc[6]=u1.z; bc[7]=u1.w;
            }
            #pragma unroll
            for (int i = 0; i < 4; i++)
                #pragma unroll
                for (int j = 0; j < 8; j++)
                    acc[i][j] += an[i]*bn[j];
        }
        __syncthreads();
    }
    #pragma unroll
    for (int i = 0; i < 4; i++) {
        int row = m0 + ty*4 + i;
        float* cp = g_Hc + (long)row*N;
        int c0 = tx*4, c1 = 64 + tx*4;
        if (c0 < N) *(float4*)(cp + c0) = make_float4(acc[i][0],acc[i][1],acc[i][2],acc[i][3]);
        if (c1 < N) *(float4*)(cp + c1) = make_float4(acc[i][4],acc[i][5],acc[i][6],acc[i][7]);
    }
}

// ================= flash attention, 32-row q-tiles =================
__global__ __launch_bounds__(256)
void attn_kernel(const int* __restrict__ lengths) {
    extern __shared__ float sm[];
    float* Qs  = sm;
    float* KVs = sm + 32*128;
    float* Ps  = sm + 32*128 + 64*128;

    int b  = blockIdx.y;
    int qt = 7 - blockIdx.x;
    int q0 = qt * 32;
    int len = lengths[b];
    if (q0 >= len) return;

    int tid = threadIdx.x;
    int tx = tid & 15, ty = tid >> 4;
    float4* Q4  = (float4*)Qs;
    float4* KV4 = (float4*)KVs;
    float4* P4  = (float4*)Ps;
    int swa = (ty >> 1) & 7;
    int swb = tx & 7;

    const float4* Qg = (const float4*)(g_Q + (long)(b*cT + q0)*cE);
    #pragma unroll
    for (int i = 0; i < 4; i++) {
        int idx = tid + i*256;
        int r = idx >> 5, c = idx & 31;
        Q4[r*32 + (c ^ ((r>>2)&7))] = Qg[r*32 + c];
    }
    float O[2][8] = {};
    float mr[2], lr[2];
    #pragma unroll
    for (int i = 0; i < 2; i++) { mr[i] = -1e30f; lr[i] = 0.f; }
    __syncthreads();

    int ktmax = min(q0 >> 6, ((len + 63) >> 6) - 1);
    for (int kt = 0; kt <= ktmax; kt++) {
        const float4* Kg = (const float4*)(g_K + (long)(b*cT + kt*64)*cE);
        #pragma unroll
        for (int i = 0; i < 8; i++) {
            int idx = tid + i*256;
            int r = idx >> 5, c = idx & 31;
            KV4[r*32 + (c ^ ((r>>2)&7))] = Kg[r*32 + c];
        }
        __syncthreads();
        float s[2][4] = {};
        #pragma unroll 4
        for (int c = 0; c < 32; c++) {
            float4 a4[2], b4[4];
            #pragma unroll
            for (int i = 0; i < 2; i++) a4[i] = Q4[(ty*2 + i)*32 + (c ^ swa)];
            #pragma unroll
            for (int j = 0; j < 4; j++) b4[j] = KV4[(tx*4 + j)*32 + (c ^ swb)];
            #pragma unroll
            for (int i = 0; i < 2; i++)
                #pragma unroll
                for (int j = 0; j < 4; j++) {
                    s[i][j] += a4[i].x*b4[j].x;
                    s[i][j] += a4[i].y*b4[j].y;
                    s[i][j] += a4[i].z*b4[j].z;
                    s[i][j] += a4[i].w*b4[j].w;
                }
        }
        int kbase = kt*64;
        #pragma unroll
        for (int i = 0; i < 2; i++) {
            int q = q0 + ty*2 + i;
            #pragma unroll
            for (int j = 0; j < 4; j++) {
                int k = kbase + tx*4 + j;
                if (k > q || k >= len) s[i][j] = -1e30f;
            }
        }
        #pragma unroll
        for (int i = 0; i < 2; i++) {
            float m2 = fmaxf(fmaxf(s[i][0], s[i][1]), fmaxf(s[i][2], s[i][3]));
            #pragma unroll
            for (int o = 1; o < 16; o <<= 1)
                m2 = fmaxf(m2, __shfl_xor_sync(0xffffffffu, m2, o));
            float mn = fmaxf(mr[i], m2);
            float al = __expf(mr[i] - mn);
            mr[i] = mn;
            float r = 0.f;
            #pragma unroll
            for (int j = 0; j < 4; j++) {
                float p = __expf(s[i][j] - mn);
                s[i][j] = p; r += p;
            }
            #pragma unroll
            for (int o = 1; o < 16; o <<= 1)
                r += __shfl_xor_sync(0xffffffffu, r, o);
            lr[i] = lr[i]*al + r;
            #pragma unroll
            for (int j = 0; j < 8; j++) O[i][j] *= al;
        }
        #pragma unroll
        for (int i = 0; i < 2; i++)
            #pragma unroll
            for (int j = 0; j < 4; j++)
                Ps[(ty*2 + i)*68 + tx*4 + j] = s[i][j];
        __syncthreads();
        const float4* Vg = (const float4*)(g_V + (long)(b*cT + kt*64)*cE);
        #pragma unroll
        for (int i = 0; i < 8; i++) {
            int idx = tid + i*256;
            int r = idx >> 5, c = idx & 31;
            KV4[r*32 + (c ^ ((r>>2)&7))] = Vg[r*32 + c];
        }
        __syncthreads();
        #pragma unroll 2
        for (int c4 = 0; c4 < 16; c4++) {
            float4 p4[2];
            #pragma unroll
            for (int i = 0; i < 2; i++) p4[i] = P4[(ty*2 + i)*17 + c4];
            int X = c4 & 7;
            #pragma unroll
            for (int m = 0; m < 4; m++) {
                int kk = c4*4 + m;
                float4 v0 = KV4[kk*32 + (tx ^ X)];
                float4 v1 = KV4[kk*32 + ((tx + 16) ^ X)];
                #pragma unroll
                for (int i = 0; i < 2; i++) {
                    float p = (m == 0) ? p4[i].x : (m == 1) ? p4[i].y
                            : (m == 2) ? p4[i].z : p4[i].w;
                    O[i][0] += p*v0.x; O[i][1] += p*v0.y;
                    O[i][2] += p*v0.z; O[i][3] += p*v0.w;
                    O[i][4] += p*v1.x; O[i][5] += p*v1.y;
                    O[i][6] += p*v1.z; O[i][7] += p*v1.w;
                }
            }
        }
        __syncthreads();
    }
    float* AHg = g_AH + (long)(b*cT + q0)*cE;
    #pragma unroll
    for (int i = 0; i < 2; i++) {
        float inv = 1.f / lr[i];
        float* op = AHg + (long)(ty*2 + i)*cE;
        *(float4*)(op + tx*4)      = make_float4(O[i][0]*inv, O[i][1]*inv, O[i][2]*inv, O[i][3]*inv);
        *(float4*)(op + 64 + tx*4) = make_float4(O[i][4]*inv, O[i][5]*inv, O[i][6]*inv, O[i][7]*inv);
    }
}

// ================= MLP: k-major As, 4 blocks/SM, two 64-row passes =================
__global__ __launch_bounds__(256, 4)
void mlp_kernel(const int* __restrict__ xs, const int* __restrict__ lengths,
                const int* __restrict__ acts, const int* __restrict__ dest,
                const int* __restrict__ adj, const int* __restrict__ seg,
                const int* __restrict__ stp, const float* __restrict__ loc,
                const float* __restrict__ TD,
                const float* __restrict__ W2, const float* __restrict__ b2,
                const float* __restrict__ W3, const float* __restrict__ b3,
                const float* __restrict__ obb1, const float* __restrict__ obW2,
                const float* __restrict__ obb2, float* __restrict__ out) {
    extern __shared__ float sh[];
    float* Bs    = sh;                 // [100][64]   k-major
    float* As    = sh + 100*64;        // [100][64]   k-major h1
    float* sFeat = As + 100*64;        // [128] float4
    float* sP4   = sFeat + 128*4;      // [100] float4
    float* sW3   = sP4 + 400;          // [64]
    float* sB2   = sW3 + 64;           // [64]
    float* sLog  = sB2 + 64;           // [64]
    float* sMisc = sLog + 64;          // [4]
    float* sSt = As;                   // alias [192]
    float* sSm = As + 192;             // alias [100]
    __shared__ int sLast;
    __shared__ float rr[64];

    int b = blockIdx.y;
    int len = lengths[b];
    int t0 = blockIdx.x * 16;
    int tid = threadIdx.x;
    bool active = (t0 < len - 1);
    float bsum = 0.f;

    if (active) {
        int tmax = min(t0 + 16, len - 1);
        for (int i = tid; i < 100*64; i += 256) {
            int k = i >> 6, n = i & 63;
            Bs[i] = (n < 50) ? W2[k*50 + n] : 0.f;
        }
        if (tid < cHID) {
            sP4[tid*4 + 0] = g_Db[b*cHID + tid] + g_Cv[tid];
            sP4[tid*4 + 1] = g_Ad[tid];
            sP4[tid*4 + 2] = g_Ax[tid];
            sP4[tid*4 + 3] = g_Ay[tid];
        }
        if (tid >= 128 && tid < 192) {
            int j = tid - 128;
            sW3[j] = (j < 50) ? W3[j] : 0.f;
            sB2[j] = (j < 50) ? b2[j] : 0.f;
        }
        if (tid >= 192) {
            int j = tid - 192;
            sSt[j]      = g_sparts[j*3];
            sSt[64+j]   = g_sparts[j*3+1];
            sSt[128+j]  = g_sparts[j*3+2];
        }
        if (tid >= 100 && tid < 125) {
            int i = tid - 100;
            sSm[i]    = g_u1[i];  sSm[25+i] = g_w1b[i];
            sSm[50+i] = obW2[i];  sSm[75+i] = obb1[i];
        }
        if (tid == 125) sMisc[2] = b3[0] + obb2[0];
        __syncthreads();
        if (tid == 0) {
            float s = 0.f, ss = 0.f, c = 0.f;
            for (int i = 0; i < 64; i++) { s += sSt[i]; ss += sSt[64+i]; c += sSt[128+i]; }
            float mean = s / c;
            float var = (ss - c*mean*mean) / (c - 1.f);
            sMisc[0] = mean;
            sMisc[1] = 1.f / (sqrtf(var) + 1e-6f);
        }
        __syncthreads();

        if (tid < 128) {
            int tl = tid >> 3, d = tid & 7;
            int t = t0 + tl;
            int x = xs[b*cT + t];
            int nb = adj[x*cDEG + d];
            int db_ = dest[b];
            float nx = loc[nb*2], ny = loc[nb*2 + 1];
            float dx = loc[db_*2], dy = loc[db_*2 + 1];
            float cx = loc[x*2],  cy = loc[x*2 + 1];
            float dist = (fabsf(nx - dx) + fabsf(ny - dy)) * 100.f;
            float vx = nx - cx, vy = ny - cy;
            float inv = 1.f / (sqrtf(vx*vx + vy*vy) + 1e-8f);
            float mf = (nb != 0) ? 1.f : 0.f;
            float tt = TD[(long)seg[x*cDEG + d]*cNBUCKET + stp[0]];
            float ttw = (tt - sMisc[0]) * sMisc[1];
            float ob = 0.f;
            #pragma unroll
            for (int i = 0; i < 25; i++) {
                float z = mf*(ttw*sSm[i] + sSm[25+i]) + sSm[75+i];
                ob += fmaxf(z, 0.f) * sSm[50+i];
            }
            ((float4*)sFeat)[tid] = make_float4(dist, vx*inv, vy*inv, ob);
        }
        __syncthreads();

        int tx = tid & 15, ty = tid >> 4;
        float w3v[4], b2v[4];
        #pragma unroll
        for (int j = 0; j < 4; j++) { w3v[j] = sW3[tx*4 + j]; b2v[j] = sB2[tx*4 + j]; }
        float lb = sMisc[2];
        int frow = tid & 63;
        int k0f  = tid >> 6;

        #pragma unroll
        for (int pass = 0; pass < 2; pass++) {
            int rbase = pass*64;
            {
                float4 f = ((float4*)sFeat)[rbase + frow];
                const float* HcRow = g_Hc +
                    ((long)(b*cT + t0) + ((rbase + frow) >> 3))*cHID;
                #pragma unroll
                for (int i = 0; i < 25; i++) {
                    int k = k0f + 4*i;
                    float4 p = ((float4*)sP4)[k];
                    float h = HcRow[k] + p.x + f.x*p.y + f.y*p.z + f.z*p.w;
                    As[k*64 + frow] = fmaxf(h, 0.f);
                }
            }
            __syncthreads();
            const float4* A4 = (const float4*)As;
            const float4* B4 = (const float4*)Bs;
            float acc[4][4] = {};
            #pragma unroll 5
            for (int c2 = 0; c2 < 50; c2++) {
                float4 a0 = A4[(2*c2)*16 + ty];
                float4 a1 = A4[(2*c2 + 1)*16 + ty];
                float4 b0 = B4[(2*c2)*16 + tx];
                float4 b1 = B4[(2*c2 + 1)*16 + tx];
                acc[0][0] += a0.x*b0.x; acc[0][1] += a0.x*b0.y;
                acc[0][2] += a0.x*b0.z; acc[0][3] += a0.x*b0.w;
                acc[1][0] += a0.y*b0.x; acc[1][1] += a0.y*b0.y;
                acc[1][2] += a0.y*b0.z; acc[1][3] += a0.y*b0.w;
                acc[2][0] += a0.z*b0.x; acc[2][1] += a0.z*b0.y;
                acc[2][2] += a0.z*b0.z; acc[2][3] += a0.z*b0.w;
                acc[3][0] += a0.w*b0.x; acc[3][1] += a0.w*b0.y;
                acc[3][2] += a0.w*b0.z; acc[3][3] += a0.w*b0.w;
                acc[0][0] += a1.x*b1.x; acc[0][1] += a1.x*b1.y;
                acc[0][2] += a1.x*b1.z; acc[0][3] += a1.x*b1.w;
                acc[1][0] += a1.y*b1.x; acc[1][1] += a1.y*b1.y;
                acc[1][2] += a1.y*b1.z; acc[1][3] += a1.y*b1.w;
                acc[2][0] += a1.z*b1.x; acc[2][1] += a1.z*b1.y;
                acc[2][2] += a1.z*b1.z; acc[2][3] += a1.z*b1.w;
                acc[3][0] += a1.w*b1.x; acc[3][1] += a1.w*b1.y;
                acc[3][2] += a1.w*b1.z; acc[3][3] += a1.w*b1.w;
            }
            #pragma unroll
            for (int i = 0; i < 4; i++) {
                float part = 0.f;
                #pragma unroll
                for (int j = 0; j < 4; j++)
                    part += fmaxf(acc[i][j] + b2v[j], 0.f) * w3v[j];
                #pragma unroll
                for (int o = 8; o > 0; o >>= 1)
                    part += __shfl_xor_sync(0xffffffffu, part, o);
                if (tx == 0) {
                    int row = ty*4 + i;
                    sLog[row] = part + ((float4*)sFeat)[rbase + row].w + lb;
                }
            }
            __syncthreads();
            if (tid < 32) {
                float nll = 0.f;
                if (tid < 8) {
                    int t = t0 + pass*8 + tid;
                    if (t < tmax) {
                        float l0[8];
                        #pragma unroll
                        for (int i = 0; i < 8; i++) l0[i] = sLog[tid*8 + i];
                        float m = l0[0];
                        #pragma unroll
                        for (int i = 1; i < 8; i++) m = fmaxf(m, l0[i]);
                        float s = 0.f;
                        #pragma unroll
                        for (int i = 0; i < 8; i++) s += __expf(l0[i] - m);
                        int a = acts[b*cTM1 + t];
                        nll = (m + __logf(s)) - l0[a];
                    }
                }
                bsum += nll;
            }
        }
        if (tid < 32) {
            #pragma unroll
            for (int o = 16; o > 0; o >>= 1)
                bsum += __shfl_xor_sync(0xffffffffu, bsum, o);
            if (tid == 0) g_pparts[blockIdx.x*cB + b] = bsum;
        }
    } else {
        if (tid == 0) g_pparts[blockIdx.x*cB + b] = 0.f;
    }

    __syncthreads();
    __threadfence();
    if (tid == 0) {
        int n = atomicAdd(&g_done, 1);
        sLast = (n == cCH*cB - 1) ? 1 : 0;
    }
    __syncthreads();
    if (sLast) {
        __threadfence();
        if (tid < 64) {
            float s = 0.f;
            #pragma unroll
            for (int c = 0; c < cCH; c++) s += g_pparts[c*cB + tid];
            rr[tid] = s / (float)(lengths[tid] - 1);
        }
        __syncthreads();
        for (int o = 32; o > 0; o >>= 1) {
            if (tid < o && tid + o < 64) rr[tid] += rr[tid + o];
            __syncthreads();
        }
        if (tid == 0) out[0] = rr[0];
    }
}

// ---------------- launch ----------------
extern "C" void kernel_launch(void* const* d_in, const int* in_sizes, int n_in,
                              void* d_out, int out_size) {
    const int*   xs      = (const int*)  d_in[0];
    const int*   lengths = (const int*)  d_in[1];
    const int*   acts    = (const int*)  d_in[2];
    const int*   dest    = (const int*)  d_in[3];
    const int*   adj     = (const int*)  d_in[4];
    const int*   seg     = (const int*)  d_in[5];
    const int*   stp     = (const int*)  d_in[6];
    const float* loc     = (const float*)d_in[7];
    const float* TD      = (const float*)d_in[8];
    const float* emb     = (const float*)d_in[9];
    const float* Wq      = (const float*)d_in[10];
    const float* Wk      = (const float*)d_in[11];
    const float* Wv      = (const float*)d_in[12];
    const float* Wo      = (const float*)d_in[13];
    const float* distW   = (const float*)d_in[14];
    const float* distb   = (const float*)d_in[15];
    const float* dirW    = (const float*)d_in[16];
    const float* dirb    = (const float*)d_in[17];
    const float* ttW     = (const float*)d_in[18];
    const float* ttb     = (const float*)d_in[19];
    const float* obW1    = (const float*)d_in[20];
    const float* obb1    = (const float*)d_in[21];
    const float* obW2    = (const float*)d_in[22];
    const float* obb2    = (const float*)d_in[23];
    const float* W1      = (const float*)d_in[24];
    const float* omb1    = (const float*)d_in[25];
    const float* W2      = (const float*)d_in[26];
    const float* b2      = (const float*)d_in[27];
    const float* W3      = (const float*)d_in[28];
    const float* b3      = (const float*)d_in[29];

    const int ASMEM = (32*128 + 64*128 + 32*68) * 4;   // 57856 B
    cudaFuncSetAttribute(attn_kernel, cudaFuncAttributeMaxDynamicSharedMemorySize, ASMEM);
    const int MSMEM = (100*64 + 100*64 + 128*4 + 100*4 + 64 + 64 + 64 + 4) * 4; // 55536 B
    cudaFuncSetAttribute(mlp_kernel, cudaFuncAttributeMaxDynamicSharedMemorySize, MSMEM);

    // 1) QKV (64-row tiles) + setup tail
    qkv_setup_kernel<<<dim3(3, 256 + 161), 256>>>(
        xs, emb, Wq, Wk, Wv, lengths,
        Wo, W1, dest, distW, distb, dirW, dirb, ttW, ttb, obW1, omb1,
        adj, seg, TD, stp);

    // 2) flash attention, 32-row q-tiles
    attn_kernel<<<dim3(8, cB), 256, ASMEM>>>(lengths);

    // 3) Hc = AH @ WoW1
    hc_gemm<<<dim3(1, 128), 512>>>(lengths);

    // 4) MLP + NLL + fused final reduction
    mlp_kernel<<<dim3(cCH, cB), 256, MSMEM>>>(xs, lengths, acts, dest, adj, seg, stp,
                                              loc, TD, W2, b2, W3, b3,
                                              obb1, obW2, obb2, (float*)d_out);
}